// round 14
// baseline (speedup 1.0000x reference)
#include <cuda_runtime.h>
#include <cuda_fp16.h>

#define Nn 100000
#define Gg 1000
#define Ee 1600000
#define EGe 16000
#define SCAN_BS 512
#define NB1 ((Nn + SCAN_BS - 1) / SCAN_BS)
#define HSTR 136   // halves per staged row (272B stride, conflict-free ldmatrix)

// ---------------- scratch (device globals; no runtime allocation) ----------------
static __device__ __align__(16) __half g_h1h[Nn*128];   // x @ W1, fp16 storage
static __device__ __align__(16) float g_asrc1[Nn*4];
static __device__ __align__(16) float g_adst1[Nn*4];
static __device__ __align__(16) float g_h2[Gg*128];
static __device__ __align__(16) float g_xgf[Gg*128];    // GAT2 final (with bias2)
static __device__ __align__(16) float g_adj[Gg*128];    // adjacent-group mean
static __device__ __align__(16) float g_asrc2[Gg*4];
static __device__ __align__(16) float g_adst2[Gg*4];
static __device__ float g_cnt[Gg];

// CSR scratch
static __device__ int g_deg1[Nn];
static __device__ int g_row1[Nn + 1];
static __device__ int g_cur1[Nn];
static __device__ int g_csr1[Ee + Nn];
static __device__ int g_bsum1[NB1];
static __device__ int g_row2[Gg + 1];
static __device__ int g_csr2[EGe + Gg];

__device__ __forceinline__ void redAddV4(float* p, float a, float b, float c, float d) {
    asm volatile("red.global.add.v4.f32 [%0], {%1, %2, %3, %4};"
                 :: "l"(p), "f"(a), "f"(b), "f"(c), "f"(d) : "memory");
}
__device__ __forceinline__ unsigned s2u(const void* p) {
    unsigned a;
    asm("{ .reg .u64 t; cvta.to.shared.u64 t, %1; cvt.u32.u64 %0, t; }" : "=r"(a) : "l"(p));
    return a;
}

// ---------------- branch-B init: graph-1 degrees only ----------------
__global__ void init_kernel() {
    int i = blockIdx.x * blockDim.x + threadIdx.x;
    if (i < Nn) g_deg1[i] = 1;            // self-loop baked into degree
}

// ---------------- graph-1 CSR build ----------------
__global__ void hist_kernel(const int* __restrict__ dst) {
    int e = blockIdx.x * blockDim.x + threadIdx.x;
    if (e < Ee) atomicAdd(&g_deg1[dst[e]], 1);
}

__global__ void scan1_kernel() {
    __shared__ int s[SCAN_BS];
    int tid = threadIdx.x;
    int i = blockIdx.x * SCAN_BS + tid;
    int v = (i < Nn) ? g_deg1[i] : 0;
    s[tid] = v;
    __syncthreads();
    #pragma unroll
    for (int off = 1; off < SCAN_BS; off <<= 1) {
        int t = (tid >= off) ? s[tid - off] : 0;
        __syncthreads();
        s[tid] += t;
        __syncthreads();
    }
    if (i < Nn) g_row1[i] = s[tid] - v;
    if (tid == SCAN_BS - 1) g_bsum1[blockIdx.x] = s[tid];
}

__global__ void scan2_kernel() {
    __shared__ int s[256];
    int tid = threadIdx.x;
    int v = (tid < NB1) ? g_bsum1[tid] : 0;
    s[tid] = v;
    __syncthreads();
    #pragma unroll
    for (int off = 1; off < 256; off <<= 1) {
        int t = (tid >= off) ? s[tid - off] : 0;
        __syncthreads();
        s[tid] += t;
        __syncthreads();
    }
    if (tid < NB1) g_bsum1[tid] = s[tid] - v;
}

__global__ void scan3_kernel() {
    int i = blockIdx.x * SCAN_BS + threadIdx.x;
    if (i < Nn) {
        int r = g_row1[i] + g_bsum1[blockIdx.x];
        g_row1[i] = r;
        g_cur1[i] = r;
    }
    if (i == 0) g_row1[Nn] = Ee + Nn;
}

__global__ void scatter_kernel(const int* __restrict__ src, const int* __restrict__ dst) {
    int e = blockIdx.x * blockDim.x + threadIdx.x;
    if (e >= Ee + Nn) return;
    int si, di;
    if (e < Ee) { si = src[e]; di = dst[e]; } else { si = di = e - Ee; }
    int pos = atomicAdd(&g_cur1[di], 1);
    g_csr1[pos] = si;
}

// ---------------- graph-2 CSR build + group-state init (head of s3 chain) ----------
__global__ void build_csr2_kernel(const int* __restrict__ eig) {
    __shared__ int sdeg[1024];
    __shared__ int sscan[1024];
    __shared__ int scur[Gg];
    int t = threadIdx.x;
    for (int i = t; i < Gg*128; i += 1024) g_adj[i] = 0.f;
    if (t < Gg) g_cnt[t] = 0.f;
    sdeg[t] = (t < Gg) ? 1 : 0;
    __syncthreads();
    for (int e = t; e < EGe; e += 1024) atomicAdd(&sdeg[eig[EGe + e]], 1);
    __syncthreads();
    int v = sdeg[t];
    sscan[t] = v;
    __syncthreads();
    #pragma unroll
    for (int off = 1; off < 1024; off <<= 1) {
        int tv = (t >= off) ? sscan[t - off] : 0;
        __syncthreads();
        sscan[t] += tv;
        __syncthreads();
    }
    int excl = sscan[t] - v;
    if (t < Gg) { g_row2[t] = excl; scur[t] = excl; }
    if (t == 0) g_row2[Gg] = EGe + Gg;
    __syncthreads();
    for (int e = t; e < EGe + Gg; e += 1024) {
        int si, di;
        if (e < EGe) { si = eig[e]; di = eig[EGe + e]; } else { si = di = e - EGe; }
        int pos = atomicAdd(&scur[di], 1);
        g_csr2[pos] = si;
    }
}

// ---------------- graph-1 GEMM via fp16 HMMA (m16n8k16), fused att scores ----------
__global__ void __launch_bounds__(256) hgemm1_kernel(
        const float* __restrict__ A, const float* __restrict__ B,
        const float* __restrict__ att_s, const float* __restrict__ att_d, int n) {
    extern __shared__ __half sh[];
    __half* Bh = sh;                    // [128 n][HSTR k]
    __half* Ah = sh + 128*HSTR;         // [128 row][HSTR k]
    int t = threadIdx.x;
    int rowBase = blockIdx.x * 128;

    for (int idx = t*4; idx < 128*128; idx += 256*4) {
        int k = idx >> 7, nc = idx & 127;
        float4 b = *(const float4*)(B + idx);
        Bh[(nc+0)*HSTR + k] = __float2half_rn(b.x);
        Bh[(nc+1)*HSTR + k] = __float2half_rn(b.y);
        Bh[(nc+2)*HSTR + k] = __float2half_rn(b.z);
        Bh[(nc+3)*HSTR + k] = __float2half_rn(b.w);
    }
    for (int idx = t*4; idx < 128*128; idx += 256*4) {
        int r = idx >> 7, k = idx & 127;
        int row = rowBase + r;
        float4 a = (row < n) ? *(const float4*)(A + (size_t)row*128 + k)
                             : make_float4(0.f, 0.f, 0.f, 0.f);
        __half2* dp = (__half2*)&Ah[r*HSTR + k];
        dp[0] = __floats2half2_rn(a.x, a.y);
        dp[1] = __floats2half2_rn(a.z, a.w);
    }
    __syncthreads();

    int warp = t >> 5, lane = t & 31;
    int g = lane >> 2, tg = lane & 3;
    unsigned aBase = s2u(&Ah[(warp*16 + (lane & 15))*HSTR + (lane >> 4)*8]);
    unsigned bBase = s2u(&Bh[(lane & 7)*HSTR + ((lane >> 3) & 1)*8]);

    float c[16][4];
    #pragma unroll
    for (int i = 0; i < 16; i++)
        #pragma unroll
        for (int j = 0; j < 4; j++) c[i][j] = 0.f;

    #pragma unroll
    for (int ks = 0; ks < 8; ks++) {
        unsigned a0, a1, a2, a3;
        asm volatile("ldmatrix.sync.aligned.m8n8.x4.shared.b16 {%0,%1,%2,%3}, [%4];"
                     : "=r"(a0), "=r"(a1), "=r"(a2), "=r"(a3)
                     : "r"(aBase + ks*32));
        #pragma unroll
        for (int nt = 0; nt < 16; nt++) {
            unsigned b0, b1;
            asm volatile("ldmatrix.sync.aligned.m8n8.x2.shared.b16 {%0,%1}, [%2];"
                         : "=r"(b0), "=r"(b1)
                         : "r"(bBase + nt*8*(HSTR*2) + ks*32));
            asm volatile("mma.sync.aligned.m16n8k16.row.col.f32.f16.f16.f32 "
                         "{%0,%1,%2,%3}, {%4,%5,%6,%7}, {%8,%9}, {%0,%1,%2,%3};"
                         : "+f"(c[nt][0]), "+f"(c[nt][1]), "+f"(c[nt][2]), "+f"(c[nt][3])
                         : "r"(a0), "r"(a1), "r"(a2), "r"(a3), "r"(b0), "r"(b1));
        }
    }

    int row0 = rowBase + warp*16 + g;
    int row1 = row0 + 8;
    bool v0 = row0 < n, v1 = row1 < n;
    float ps0[4] = {0,0,0,0}, ps1[4] = {0,0,0,0};
    float pd0[4] = {0,0,0,0}, pd1[4] = {0,0,0,0};
    #pragma unroll
    for (int nt = 0; nt < 16; nt++) {
        int col = nt*8 + tg*2;
        float sa0 = __ldg(att_s + col), sa1 = __ldg(att_s + col + 1);
        float da0 = __ldg(att_d + col), da1 = __ldg(att_d + col + 1);
        int h = nt >> 2;
        ps0[h] += c[nt][0]*sa0 + c[nt][1]*sa1;
        pd0[h] += c[nt][0]*da0 + c[nt][1]*da1;
        ps1[h] += c[nt][2]*sa0 + c[nt][3]*sa1;
        pd1[h] += c[nt][2]*da0 + c[nt][3]*da1;
        if (v0) *(__half2*)(g_h1h + (size_t)row0*128 + col) = __floats2half2_rn(c[nt][0], c[nt][1]);
        if (v1) *(__half2*)(g_h1h + (size_t)row1*128 + col) = __floats2half2_rn(c[nt][2], c[nt][3]);
    }
    #pragma unroll
    for (int h = 0; h < 4; h++) {
        ps0[h] += __shfl_xor_sync(0xffffffffu, ps0[h], 1);
        ps0[h] += __shfl_xor_sync(0xffffffffu, ps0[h], 2);
        pd0[h] += __shfl_xor_sync(0xffffffffu, pd0[h], 1);
        pd0[h] += __shfl_xor_sync(0xffffffffu, pd0[h], 2);
        ps1[h] += __shfl_xor_sync(0xffffffffu, ps1[h], 1);
        ps1[h] += __shfl_xor_sync(0xffffffffu, ps1[h], 2);
        pd1[h] += __shfl_xor_sync(0xffffffffu, pd1[h], 1);
        pd1[h] += __shfl_xor_sync(0xffffffffu, pd1[h], 2);
    }
    if (tg == 0) {
        if (v0) {
            #pragma unroll
            for (int h = 0; h < 4; h++) { g_asrc1[row0*4 + h] = ps0[h]; g_adst1[row0*4 + h] = pd0[h]; }
        }
        if (v1) {
            #pragma unroll
            for (int h = 0; h < 4; h++) { g_asrc1[row1*4 + h] = ps1[h]; g_adst1[row1*4 + h] = pd1[h]; }
        }
    }
}

// ---------------- graph-2 GEMM (plain FFMA, proven): fp32 h2 + att scores ----------
__global__ void gemm2_k128(const float* __restrict__ A, const float* __restrict__ B,
                           const float* __restrict__ att_s, const float* __restrict__ att_d,
                           int n) {
    __shared__ float As[16][68];
    __shared__ float Bs[16][128];
    int t = threadIdx.x;
    int rowBase = blockIdx.x * 64;
    int tr = t >> 5, tc = t & 31;
    float acc[8][4];
    #pragma unroll
    for (int i = 0; i < 8; i++)
        #pragma unroll
        for (int j = 0; j < 4; j++) acc[i][j] = 0.f;

    for (int kt = 0; kt < 128; kt += 16) {
        int ar = t >> 2;
        int ac = (t & 3) << 2;
        int row = rowBase + ar;
        float4 av = (row < n) ? *(const float4*)(A + row*128 + kt + ac)
                              : make_float4(0.f, 0.f, 0.f, 0.f);
        As[ac+0][ar] = av.x; As[ac+1][ar] = av.y;
        As[ac+2][ar] = av.z; As[ac+3][ar] = av.w;
        int br = t >> 4;
        int bc = (t & 15) << 3;
        float4 b0 = *(const float4*)(B + (kt + br)*128 + bc);
        float4 b1 = *(const float4*)(B + (kt + br)*128 + bc + 4);
        *(float4*)&Bs[br][bc]     = b0;
        *(float4*)&Bs[br][bc + 4] = b1;
        __syncthreads();
        #pragma unroll
        for (int kk = 0; kk < 16; kk++) {
            float4 a0 = *(const float4*)&As[kk][tr*8];
            float4 a1 = *(const float4*)&As[kk][tr*8 + 4];
            float4 b  = *(const float4*)&Bs[kk][tc*4];
            float av_[8] = {a0.x,a0.y,a0.z,a0.w,a1.x,a1.y,a1.z,a1.w};
            #pragma unroll
            for (int i = 0; i < 8; i++) {
                acc[i][0] += av_[i]*b.x; acc[i][1] += av_[i]*b.y;
                acc[i][2] += av_[i]*b.z; acc[i][3] += av_[i]*b.w;
            }
        }
        __syncthreads();
    }
    float4 sa = *(const float4*)(att_s + tc*4);
    float4 da = *(const float4*)(att_d + tc*4);
    int head = tc >> 3;
    #pragma unroll
    for (int i = 0; i < 8; i++) {
        int row = rowBase + tr*8 + i;
        if (row < n) {
            *(float4*)(g_h2 + row*128 + tc*4) =
                make_float4(acc[i][0], acc[i][1], acc[i][2], acc[i][3]);
            float ps = acc[i][0]*sa.x + acc[i][1]*sa.y + acc[i][2]*sa.z + acc[i][3]*sa.w;
            float pd = acc[i][0]*da.x + acc[i][1]*da.y + acc[i][2]*da.z + acc[i][3]*da.w;
            #pragma unroll
            for (int off = 4; off >= 1; off >>= 1) {
                ps += __shfl_xor_sync(0xffffffffu, ps, off);
                pd += __shfl_xor_sync(0xffffffffu, pd, off);
            }
            if ((tc & 7) == 0) {
                g_asrc2[row*4 + head] = ps;
                g_adst2[row*4 + head] = pd;
            }
        }
    }
}

// ---------------- graph-1: fused agg + bias + bilinear + FC, HALF-warp per node ----
// 256 threads, 16 nodes/block. Each 16-lane half-warp owns a node; each lane owns
// 8 fp16 channels (one 16B gather per edge). 2x edges in flight per warp vs R13.
__global__ void csr_agg1_final_kernel(const float* __restrict__ bias1,
                                      const int* __restrict__ node_group,
                                      const float* __restrict__ Wfc,
                                      const float* __restrict__ bfc,
                                      float* __restrict__ out) {
    __shared__ float Ws[128*32];
    __shared__ float Us[16][128];
    int t = threadIdx.x;
    for (int i = t; i < 128*32; i += 256) Ws[i] = Wfc[i];
    __syncthreads();              // only block-wide sync: after weight preload

    int w = t >> 5, lane = t & 31;
    int sub = lane >> 4;          // 0/1: which node of the pair
    int sl  = lane & 15;          // sub-lane within the node's 16 lanes
    int d = blockIdx.x*16 + w*2 + sub;   // Nn % 16 == 0 -> always valid
    int start = g_row1[d], end = g_row1[d + 1];
    int hd = sl >> 2;             // lane's 8 channels sit in one head
    float adv = __ldg(&g_adst1[d*4 + hd]);
    float4 accA = make_float4(0.f, 0.f, 0.f, 0.f);
    float4 accB = make_float4(0.f, 0.f, 0.f, 0.f);
    float wsum = 0.f;
    const __half* hp = g_h1h + sl*8;

    int j = start;
    for (; j + 4 <= end; j += 4) {
        int s0 = __ldg(&g_csr1[j]);
        int s1 = __ldg(&g_csr1[j + 1]);
        int s2 = __ldg(&g_csr1[j + 2]);
        int s3 = __ldg(&g_csr1[j + 3]);
        float a0 = __ldg(&g_asrc1[s0*4 + hd]);
        float a1 = __ldg(&g_asrc1[s1*4 + hd]);
        float a2 = __ldg(&g_asrc1[s2*4 + hd]);
        float a3 = __ldg(&g_asrc1[s3*4 + hd]);
        uint4 q0 = __ldg((const uint4*)(hp + (size_t)s0*128));
        uint4 q1 = __ldg((const uint4*)(hp + (size_t)s1*128));
        uint4 q2 = __ldg((const uint4*)(hp + (size_t)s2*128));
        uint4 q3 = __ldg((const uint4*)(hp + (size_t)s3*128));
        float e0 = a0 + adv; e0 = e0 > 0.f ? e0 : 0.2f*e0;
        float e1 = a1 + adv; e1 = e1 > 0.f ? e1 : 0.2f*e1;
        float e2 = a2 + adv; e2 = e2 > 0.f ? e2 : 0.2f*e2;
        float e3 = a3 + adv; e3 = e3 > 0.f ? e3 : 0.2f*e3;
        float w0 = __expf(e0), w1 = __expf(e1), w2 = __expf(e2), w3 = __expf(e3);
        {
            float2 fx = __half22float2(*(__half2*)&q0.x), fy = __half22float2(*(__half2*)&q0.y);
            float2 fz = __half22float2(*(__half2*)&q0.z), fw = __half22float2(*(__half2*)&q0.w);
            accA.x += w0*fx.x; accA.y += w0*fx.y; accA.z += w0*fy.x; accA.w += w0*fy.y;
            accB.x += w0*fz.x; accB.y += w0*fz.y; accB.z += w0*fw.x; accB.w += w0*fw.y;
        }
        {
            float2 fx = __half22float2(*(__half2*)&q1.x), fy = __half22float2(*(__half2*)&q1.y);
            float2 fz = __half22float2(*(__half2*)&q1.z), fw = __half22float2(*(__half2*)&q1.w);
            accA.x += w1*fx.x; accA.y += w1*fx.y; accA.z += w1*fy.x; accA.w += w1*fy.y;
            accB.x += w1*fz.x; accB.y += w1*fz.y; accB.z += w1*fw.x; accB.w += w1*fw.y;
        }
        {
            float2 fx = __half22float2(*(__half2*)&q2.x), fy = __half22float2(*(__half2*)&q2.y);
            float2 fz = __half22float2(*(__half2*)&q2.z), fw = __half22float2(*(__half2*)&q2.w);
            accA.x += w2*fx.x; accA.y += w2*fx.y; accA.z += w2*fy.x; accA.w += w2*fy.y;
            accB.x += w2*fz.x; accB.y += w2*fz.y; accB.z += w2*fw.x; accB.w += w2*fw.y;
        }
        {
            float2 fx = __half22float2(*(__half2*)&q3.x), fy = __half22float2(*(__half2*)&q3.y);
            float2 fz = __half22float2(*(__half2*)&q3.z), fw = __half22float2(*(__half2*)&q3.w);
            accA.x += w3*fx.x; accA.y += w3*fx.y; accA.z += w3*fy.x; accA.w += w3*fy.y;
            accB.x += w3*fz.x; accB.y += w3*fz.y; accB.z += w3*fw.x; accB.w += w3*fw.y;
        }
        wsum += (w0 + w1) + (w2 + w3);
    }
    for (; j < end; j++) {
        int s0 = __ldg(&g_csr1[j]);
        float a0 = __ldg(&g_asrc1[s0*4 + hd]);
        uint4 q0 = __ldg((const uint4*)(hp + (size_t)s0*128));
        float e0 = a0 + adv; e0 = e0 > 0.f ? e0 : 0.2f*e0;
        float w0 = __expf(e0);
        float2 fx = __half22float2(*(__half2*)&q0.x), fy = __half22float2(*(__half2*)&q0.y);
        float2 fz = __half22float2(*(__half2*)&q0.z), fw = __half22float2(*(__half2*)&q0.w);
        accA.x += w0*fx.x; accA.y += w0*fx.y; accA.z += w0*fy.x; accA.w += w0*fy.y;
        accB.x += w0*fz.x; accB.y += w0*fz.y; accB.z += w0*fw.x; accB.w += w0*fw.y;
        wsum += w0;
    }

    float inv = 1.f / (wsum + 1e-16f);
    float4 b1a = *(const float4*)(bias1 + sl*8);
    float4 b1b = *(const float4*)(bias1 + sl*8 + 4);
    float4 xoA = make_float4(accA.x*inv + b1a.x, accA.y*inv + b1a.y,
                             accA.z*inv + b1a.z, accA.w*inv + b1a.w);
    float4 xoB = make_float4(accB.x*inv + b1b.x, accB.y*inv + b1b.y,
                             accB.z*inv + b1b.z, accB.w*inv + b1b.w);
    int g = __ldg(&node_group[d]);
    float4 gfA = *(const float4*)(g_xgf + g*128 + sl*8);
    float4 gfB = *(const float4*)(g_xgf + g*128 + sl*8 + 4);
    float4 afA = *(const float4*)(g_adj + g*128 + sl*8);
    float4 afB = *(const float4*)(g_adj + g*128 + sl*8 + 4);
    float pg = xoA.x*gfA.x + xoA.y*gfA.y + xoA.z*gfA.z + xoA.w*gfA.w
             + xoB.x*gfB.x + xoB.y*gfB.y + xoB.z*gfB.z + xoB.w*gfB.w;
    float pa = xoA.x*afA.x + xoA.y*afA.y + xoA.z*afA.z + xoA.w*afA.w
             + xoB.x*afB.x + xoB.y*afB.y + xoB.z*afB.z + xoB.w*afB.w;
    #pragma unroll
    for (int off = 8; off >= 1; off >>= 1) {    // reduce within the 16-lane half
        pg += __shfl_xor_sync(0xffffffffu, pg, off);
        pa += __shfl_xor_sync(0xffffffffu, pa, off);
    }
    float4 uA, uB;
    uA.x = xoA.x + pg*gfA.x + pa*afA.x;
    uA.y = xoA.y + pg*gfA.y + pa*afA.y;
    uA.z = xoA.z + pg*gfA.z + pa*afA.z;
    uA.w = xoA.w + pg*gfA.w + pa*afA.w;
    uB.x = xoB.x + pg*gfB.x + pa*afB.x;
    uB.y = xoB.y + pg*gfB.y + pa*afB.y;
    uB.z = xoB.z + pg*gfB.z + pa*afB.z;
    uB.w = xoB.w + pg*gfB.w + pa*afB.w;
    int slot = w*2 + sub;
    *(float4*)&Us[slot][sl*8]     = uA;
    *(float4*)&Us[slot][sl*8 + 4] = uB;
    __syncwarp();

    // FC: warp handles its 2 nodes; lane = output column
    float bfv = bfc[lane];
    int nodeBase = blockIdx.x*16 + w*2;
    #pragma unroll
    for (int nd = 0; nd < 2; nd++) {
        const float* ur = Us[w*2 + nd];
        float accO = bfv;
        #pragma unroll
        for (int k = 0; k < 128; k++) accO += ur[k] * Ws[k*32 + lane];
        out[(nodeBase + nd)*32 + lane] = accO;
    }
}

// ---------------- graph-2: fused softmax + agg + bias2, writes xgf & d_out tail ----
__global__ void csr_agg2_kernel(const float* __restrict__ bias2, float* __restrict__ dtail) {
    int gid = blockIdx.x * blockDim.x + threadIdx.x;
    int d = gid >> 5, lane = threadIdx.x & 31;
    if (d >= Gg) return;
    int start = g_row2[d], end = g_row2[d + 1];
    int hd = lane >> 3;
    float adv = __ldg(&g_adst2[d*4 + hd]);
    float4 acc = make_float4(0.f, 0.f, 0.f, 0.f);
    float wsum = 0.f;
    for (int j = start; j < end; j++) {
        int si = __ldg(&g_csr2[j]);
        float a = __ldg(&g_asrc2[si*4 + hd]);
        float4 hv = *(const float4*)(g_h2 + si*128 + lane*4);
        float e = a + adv;
        e = e > 0.f ? e : 0.2f*e;
        float w = __expf(e);
        acc.x += w*hv.x; acc.y += w*hv.y; acc.z += w*hv.z; acc.w += w*hv.w;
        wsum += w;
    }
    float inv = 1.f / (wsum + 1e-16f);
    float4 bv = *(const float4*)(bias2 + lane*4);
    float4 r = make_float4(acc.x*inv + bv.x, acc.y*inv + bv.y,
                           acc.z*inv + bv.z, acc.w*inv + bv.w);
    *(float4*)(g_xgf + d*128 + lane*4) = r;
    *(float4*)(dtail + d*128 + lane*4) = r;
}

// ---------------- adjacency mean over group edges ----------------
__global__ void adj_accum_kernel(const int* __restrict__ eg) {
    int gid = blockIdx.x * blockDim.x + threadIdx.x;
    int w = gid >> 5, lane = threadIdx.x & 31;
    if (w >= EGe) return;
    int a = eg[w];
    int b = eg[EGe + w];
    float4 v = *(const float4*)(g_xgf + b*128 + lane*4);
    redAddV4(g_adj + a*128 + lane*4, v.x, v.y, v.z, v.w);
    if (lane == 0) atomicAdd(&g_cnt[a], 1.f);
}

__global__ void adj_mean_kernel() {
    int i = blockIdx.x * blockDim.x + threadIdx.x;
    if (i < Gg*128) g_adj[i] = g_adj[i] / fmaxf(g_cnt[i >> 7], 1.f);
}

// ---------------- launch: THREE-way fork (graph-1 CSR | hgemm1 | group chain) -------
extern "C" void kernel_launch(void* const* d_in, const int* in_sizes, int n_in,
                              void* d_out, int out_size) {
    const float* x    = (const float*)d_in[0];
    const float* x_g  = (const float*)d_in[1];
    const int*   ei   = (const int*)d_in[2];
    const int*   eig  = (const int*)d_in[3];
    const int*   ngrp = (const int*)d_in[4];
    const float* W1   = (const float*)d_in[5];
    const float* as1  = (const float*)d_in[6];
    const float* ad1  = (const float*)d_in[7];
    const float* b1   = (const float*)d_in[8];
    const float* W2   = (const float*)d_in[9];
    const float* as2  = (const float*)d_in[10];
    const float* ad2  = (const float*)d_in[11];
    const float* b2   = (const float*)d_in[12];
    const float* Wfc  = (const float*)d_in[13];
    const float* bfc  = (const float*)d_in[14];
    float* out = (float*)d_out;

    const int HS_BYTES = 2 * 128 * HSTR * 2;   // 69632
    cudaFuncSetAttribute(hgemm1_kernel, cudaFuncAttributeMaxDynamicSharedMemorySize, HS_BYTES);

    cudaStream_t s2, s3;
    cudaStreamCreateWithFlags(&s2, cudaStreamNonBlocking);
    cudaStreamCreateWithFlags(&s3, cudaStreamNonBlocking);
    cudaEvent_t evFork, evA, evC;
    cudaEventCreateWithFlags(&evFork, cudaEventDisableTiming);
    cudaEventCreateWithFlags(&evA, cudaEventDisableTiming);
    cudaEventCreateWithFlags(&evC, cudaEventDisableTiming);

    cudaEventRecord(evFork, 0);
    cudaStreamWaitEvent(s2, evFork, 0);
    cudaStreamWaitEvent(s3, evFork, 0);

    // Branch B (stream 0): graph-1 CSR build
    init_kernel<<<(Nn + 255)/256, 256>>>();
    hist_kernel<<<(Ee + 255)/256, 256>>>(ei + Ee);
    scan1_kernel<<<NB1, SCAN_BS>>>();
    scan2_kernel<<<1, 256>>>();
    scan3_kernel<<<NB1, SCAN_BS>>>();

    // Branch A (s2): big GEMM
    hgemm1_kernel<<<(Nn + 127)/128, 256, HS_BYTES, s2>>>(x, W1, as1, ad1, Nn);
    cudaEventRecord(evA, s2);

    scatter_kernel<<<(Ee + Nn + 255)/256, 256>>>(ei, ei + Ee);

    // Branch C (s3): whole group-graph chain, independent of A and B
    build_csr2_kernel<<<1, 1024, 0, s3>>>(eig);
    gemm2_k128<<<(Gg + 63)/64, 256, 0, s3>>>(x_g, W2, as2, ad2, Gg);
    csr_agg2_kernel<<<(Gg*32 + 255)/256, 256, 0, s3>>>(b2, out + Nn*32);
    adj_accum_kernel<<<(EGe*32 + 255)/256, 256, 0, s3>>>(eig);
    adj_mean_kernel<<<(Gg*128 + 255)/256, 256, 0, s3>>>();
    cudaEventRecord(evC, s3);

    // join: final kernel needs all three branches
    cudaStreamWaitEvent(0, evA, 0);
    cudaStreamWaitEvent(0, evC, 0);
    csr_agg1_final_kernel<<<Nn/16, 256>>>(b1, ngrp, Wfc, bfc, out);

    cudaEventDestroy(evFork);
    cudaEventDestroy(evA);
    cudaEventDestroy(evC);
    cudaStreamDestroy(s2);
    cudaStreamDestroy(s3);
}

// round 15
// speedup vs baseline: 1.3355x; 1.3355x over previous
#include <cuda_runtime.h>
#include <cuda_fp16.h>

#define Nn 100000
#define Gg 1000
#define Ee 1600000
#define EGe 16000
#define SCAN_BS 512
#define NB1 ((Nn + SCAN_BS - 1) / SCAN_BS)   // 196
#define HSTR 136   // halves per staged row (272B stride, conflict-free ldmatrix)

// ---------------- scratch (device globals; no runtime allocation) ----------------
static __device__ __align__(16) __half g_h1h[Nn*128];   // x @ W1, fp16 storage
static __device__ __align__(16) float g_asrc1[Nn*4];
static __device__ __align__(16) float g_adst1[Nn*4];
static __device__ __align__(16) float g_h2[Gg*128];
static __device__ __align__(16) float g_xgf[Gg*128];    // GAT2 final (with bias2)
static __device__ __align__(16) float g_adj[Gg*128];    // adjacent-group mean
static __device__ __align__(16) float g_asrc2[Gg*4];
static __device__ __align__(16) float g_adst2[Gg*4];
static __device__ float g_cnt[Gg];

// CSR scratch (g_deg1 is zero at every kernel_launch entry: statically zeroed on
// first run; scan1 re-zeroes it each run after consuming it -> replay-safe)
static __device__ int g_deg1[Nn];
static __device__ int g_row1[Nn + 1];
static __device__ int g_cur1[Nn];
static __device__ int g_csr1[Ee + Nn];
static __device__ int g_bsum1[NB1];
static __device__ int g_row2[Gg + 1];
static __device__ int g_csr2[EGe + Gg];

__device__ __forceinline__ void redAddV4(float* p, float a, float b, float c, float d) {
    asm volatile("red.global.add.v4.f32 [%0], {%1, %2, %3, %4};"
                 :: "l"(p), "f"(a), "f"(b), "f"(c), "f"(d) : "memory");
}
__device__ __forceinline__ unsigned s2u(const void* p) {
    unsigned a;
    asm("{ .reg .u64 t; cvta.to.shared.u64 t, %1; cvt.u32.u64 %0, t; }" : "=r"(a) : "l"(p));
    return a;
}

// ---------------- graph-1 CSR build (no init kernel: deg starts at 0) ----------------
__global__ void hist_kernel(const int* __restrict__ dst) {
    int e = blockIdx.x * blockDim.x + threadIdx.x;
    if (e < Ee) atomicAdd(&g_deg1[dst[e]], 1);
}

// per-block exclusive scan of (deg+1); resets deg to 0 for the next replay
__global__ void scan1_kernel() {
    __shared__ int s[SCAN_BS];
    int tid = threadIdx.x;
    int i = blockIdx.x * SCAN_BS + tid;
    int v = 0;
    if (i < Nn) {
        v = g_deg1[i] + 1;     // +1 = self-loop
        g_deg1[i] = 0;         // replay-safe reset
    }
    s[tid] = v;
    __syncthreads();
    #pragma unroll
    for (int off = 1; off < SCAN_BS; off <<= 1) {
        int t = (tid >= off) ? s[tid - off] : 0;
        __syncthreads();
        s[tid] += t;
        __syncthreads();
    }
    if (i < Nn) g_row1[i] = s[tid] - v;
    if (tid == SCAN_BS - 1) g_bsum1[blockIdx.x] = s[tid];
}

// merged scan2+scan3: every block redundantly scans the 196 block sums in smem,
// then applies its offset. Removes one single-block launch bubble.
__global__ void scan23_kernel() {
    __shared__ int s[256];
    int tid = threadIdx.x;
    if (tid < 256) {
        int v = (tid < NB1) ? g_bsum1[tid] : 0;
        s[tid] = v;
    }
    __syncthreads();
    if (tid < 256) {
        #pragma unroll
        for (int off = 1; off < 256; off <<= 1) {
            int t = (tid >= off) ? s[tid - off] : 0;
            __syncthreads();
            s[tid] += t;
            __syncthreads();
        }
    } else {
        #pragma unroll
        for (int off = 1; off < 256; off <<= 1) { __syncthreads(); __syncthreads(); }
    }
    __syncthreads();
    int offBlk = (blockIdx.x > 0) ? s[blockIdx.x - 1] : 0;   // exclusive prefix
    int i = blockIdx.x * SCAN_BS + tid;
    if (i < Nn) {
        int r = g_row1[i] + offBlk;
        g_row1[i] = r;
        g_cur1[i] = r;
    }
    if (i == 0) g_row1[Nn] = Ee + Nn;
}

__global__ void scatter_kernel(const int* __restrict__ src, const int* __restrict__ dst) {
    int e = blockIdx.x * blockDim.x + threadIdx.x;
    if (e >= Ee + Nn) return;
    int si, di;
    if (e < Ee) { si = src[e]; di = dst[e]; } else { si = di = e - Ee; }
    int pos = atomicAdd(&g_cur1[di], 1);
    g_csr1[pos] = si;
}

// ---------------- graph-2 CSR build + group-state init (head of s3 chain) ----------
__global__ void build_csr2_kernel(const int* __restrict__ eig) {
    __shared__ int sdeg[1024];
    __shared__ int sscan[1024];
    __shared__ int scur[Gg];
    int t = threadIdx.x;
    for (int i = t; i < Gg*128; i += 1024) g_adj[i] = 0.f;
    if (t < Gg) g_cnt[t] = 0.f;
    sdeg[t] = (t < Gg) ? 1 : 0;
    __syncthreads();
    for (int e = t; e < EGe; e += 1024) atomicAdd(&sdeg[eig[EGe + e]], 1);
    __syncthreads();
    int v = sdeg[t];
    sscan[t] = v;
    __syncthreads();
    #pragma unroll
    for (int off = 1; off < 1024; off <<= 1) {
        int tv = (t >= off) ? sscan[t - off] : 0;
        __syncthreads();
        sscan[t] += tv;
        __syncthreads();
    }
    int excl = sscan[t] - v;
    if (t < Gg) { g_row2[t] = excl; scur[t] = excl; }
    if (t == 0) g_row2[Gg] = EGe + Gg;
    __syncthreads();
    for (int e = t; e < EGe + Gg; e += 1024) {
        int si, di;
        if (e < EGe) { si = eig[e]; di = eig[EGe + e]; } else { si = di = e - EGe; }
        int pos = atomicAdd(&scur[di], 1);
        g_csr2[pos] = si;
    }
}

// ---------------- graph-1 GEMM via fp16 HMMA (m16n8k16), fused att scores ----------
__global__ void __launch_bounds__(256) hgemm1_kernel(
        const float* __restrict__ A, const float* __restrict__ B,
        const float* __restrict__ att_s, const float* __restrict__ att_d, int n) {
    extern __shared__ __half sh[];
    __half* Bh = sh;                    // [128 n][HSTR k]
    __half* Ah = sh + 128*HSTR;         // [128 row][HSTR k]
    int t = threadIdx.x;
    int rowBase = blockIdx.x * 128;

    for (int idx = t*4; idx < 128*128; idx += 256*4) {
        int k = idx >> 7, nc = idx & 127;
        float4 b = *(const float4*)(B + idx);
        Bh[(nc+0)*HSTR + k] = __float2half_rn(b.x);
        Bh[(nc+1)*HSTR + k] = __float2half_rn(b.y);
        Bh[(nc+2)*HSTR + k] = __float2half_rn(b.z);
        Bh[(nc+3)*HSTR + k] = __float2half_rn(b.w);
    }
    for (int idx = t*4; idx < 128*128; idx += 256*4) {
        int r = idx >> 7, k = idx & 127;
        int row = rowBase + r;
        float4 a = (row < n) ? *(const float4*)(A + (size_t)row*128 + k)
                             : make_float4(0.f, 0.f, 0.f, 0.f);
        __half2* dp = (__half2*)&Ah[r*HSTR + k];
        dp[0] = __floats2half2_rn(a.x, a.y);
        dp[1] = __floats2half2_rn(a.z, a.w);
    }
    __syncthreads();

    int warp = t >> 5, lane = t & 31;
    int g = lane >> 2, tg = lane & 3;
    unsigned aBase = s2u(&Ah[(warp*16 + (lane & 15))*HSTR + (lane >> 4)*8]);
    unsigned bBase = s2u(&Bh[(lane & 7)*HSTR + ((lane >> 3) & 1)*8]);

    float c[16][4];
    #pragma unroll
    for (int i = 0; i < 16; i++)
        #pragma unroll
        for (int j = 0; j < 4; j++) c[i][j] = 0.f;

    #pragma unroll
    for (int ks = 0; ks < 8; ks++) {
        unsigned a0, a1, a2, a3;
        asm volatile("ldmatrix.sync.aligned.m8n8.x4.shared.b16 {%0,%1,%2,%3}, [%4];"
                     : "=r"(a0), "=r"(a1), "=r"(a2), "=r"(a3)
                     : "r"(aBase + ks*32));
        #pragma unroll
        for (int nt = 0; nt < 16; nt++) {
            unsigned b0, b1;
            asm volatile("ldmatrix.sync.aligned.m8n8.x2.shared.b16 {%0,%1}, [%2];"
                         : "=r"(b0), "=r"(b1)
                         : "r"(bBase + nt*8*(HSTR*2) + ks*32));
            asm volatile("mma.sync.aligned.m16n8k16.row.col.f32.f16.f16.f32 "
                         "{%0,%1,%2,%3}, {%4,%5,%6,%7}, {%8,%9}, {%0,%1,%2,%3};"
                         : "+f"(c[nt][0]), "+f"(c[nt][1]), "+f"(c[nt][2]), "+f"(c[nt][3])
                         : "r"(a0), "r"(a1), "r"(a2), "r"(a3), "r"(b0), "r"(b1));
        }
    }

    int row0 = rowBase + warp*16 + g;
    int row1 = row0 + 8;
    bool v0 = row0 < n, v1 = row1 < n;
    float ps0[4] = {0,0,0,0}, ps1[4] = {0,0,0,0};
    float pd0[4] = {0,0,0,0}, pd1[4] = {0,0,0,0};
    #pragma unroll
    for (int nt = 0; nt < 16; nt++) {
        int col = nt*8 + tg*2;
        float sa0 = __ldg(att_s + col), sa1 = __ldg(att_s + col + 1);
        float da0 = __ldg(att_d + col), da1 = __ldg(att_d + col + 1);
        int h = nt >> 2;
        ps0[h] += c[nt][0]*sa0 + c[nt][1]*sa1;
        pd0[h] += c[nt][0]*da0 + c[nt][1]*da1;
        ps1[h] += c[nt][2]*sa0 + c[nt][3]*sa1;
        pd1[h] += c[nt][2]*da0 + c[nt][3]*da1;
        if (v0) *(__half2*)(g_h1h + (size_t)row0*128 + col) = __floats2half2_rn(c[nt][0], c[nt][1]);
        if (v1) *(__half2*)(g_h1h + (size_t)row1*128 + col) = __floats2half2_rn(c[nt][2], c[nt][3]);
    }
    #pragma unroll
    for (int h = 0; h < 4; h++) {
        ps0[h] += __shfl_xor_sync(0xffffffffu, ps0[h], 1);
        ps0[h] += __shfl_xor_sync(0xffffffffu, ps0[h], 2);
        pd0[h] += __shfl_xor_sync(0xffffffffu, pd0[h], 1);
        pd0[h] += __shfl_xor_sync(0xffffffffu, pd0[h], 2);
        ps1[h] += __shfl_xor_sync(0xffffffffu, ps1[h], 1);
        ps1[h] += __shfl_xor_sync(0xffffffffu, ps1[h], 2);
        pd1[h] += __shfl_xor_sync(0xffffffffu, pd1[h], 1);
        pd1[h] += __shfl_xor_sync(0xffffffffu, pd1[h], 2);
    }
    if (tg == 0) {
        if (v0) {
            #pragma unroll
            for (int h = 0; h < 4; h++) { g_asrc1[row0*4 + h] = ps0[h]; g_adst1[row0*4 + h] = pd0[h]; }
        }
        if (v1) {
            #pragma unroll
            for (int h = 0; h < 4; h++) { g_asrc1[row1*4 + h] = ps1[h]; g_adst1[row1*4 + h] = pd1[h]; }
        }
    }
}

// ---------------- graph-2 GEMM (plain FFMA, proven): fp32 h2 + att scores ----------
__global__ void gemm2_k128(const float* __restrict__ A, const float* __restrict__ B,
                           const float* __restrict__ att_s, const float* __restrict__ att_d,
                           int n) {
    __shared__ float As[16][68];
    __shared__ float Bs[16][128];
    int t = threadIdx.x;
    int rowBase = blockIdx.x * 64;
    int tr = t >> 5, tc = t & 31;
    float acc[8][4];
    #pragma unroll
    for (int i = 0; i < 8; i++)
        #pragma unroll
        for (int j = 0; j < 4; j++) acc[i][j] = 0.f;

    for (int kt = 0; kt < 128; kt += 16) {
        int ar = t >> 2;
        int ac = (t & 3) << 2;
        int row = rowBase + ar;
        float4 av = (row < n) ? *(const float4*)(A + row*128 + kt + ac)
                              : make_float4(0.f, 0.f, 0.f, 0.f);
        As[ac+0][ar] = av.x; As[ac+1][ar] = av.y;
        As[ac+2][ar] = av.z; As[ac+3][ar] = av.w;
        int br = t >> 4;
        int bc = (t & 15) << 3;
        float4 b0 = *(const float4*)(B + (kt + br)*128 + bc);
        float4 b1 = *(const float4*)(B + (kt + br)*128 + bc + 4);
        *(float4*)&Bs[br][bc]     = b0;
        *(float4*)&Bs[br][bc + 4] = b1;
        __syncthreads();
        #pragma unroll
        for (int kk = 0; kk < 16; kk++) {
            float4 a0 = *(const float4*)&As[kk][tr*8];
            float4 a1 = *(const float4*)&As[kk][tr*8 + 4];
            float4 b  = *(const float4*)&Bs[kk][tc*4];
            float av_[8] = {a0.x,a0.y,a0.z,a0.w,a1.x,a1.y,a1.z,a1.w};
            #pragma unroll
            for (int i = 0; i < 8; i++) {
                acc[i][0] += av_[i]*b.x; acc[i][1] += av_[i]*b.y;
                acc[i][2] += av_[i]*b.z; acc[i][3] += av_[i]*b.w;
            }
        }
        __syncthreads();
    }
    float4 sa = *(const float4*)(att_s + tc*4);
    float4 da = *(const float4*)(att_d + tc*4);
    int head = tc >> 3;
    #pragma unroll
    for (int i = 0; i < 8; i++) {
        int row = rowBase + tr*8 + i;
        if (row < n) {
            *(float4*)(g_h2 + row*128 + tc*4) =
                make_float4(acc[i][0], acc[i][1], acc[i][2], acc[i][3]);
            float ps = acc[i][0]*sa.x + acc[i][1]*sa.y + acc[i][2]*sa.z + acc[i][3]*sa.w;
            float pd = acc[i][0]*da.x + acc[i][1]*da.y + acc[i][2]*da.z + acc[i][3]*da.w;
            #pragma unroll
            for (int off = 4; off >= 1; off >>= 1) {
                ps += __shfl_xor_sync(0xffffffffu, ps, off);
                pd += __shfl_xor_sync(0xffffffffu, pd, off);
            }
            if ((tc & 7) == 0) {
                g_asrc2[row*4 + head] = ps;
                g_adst2[row*4 + head] = pd;
            }
        }
    }
}

// ---------------- graph-1: fused agg + bias + bilinear + FC, warp per node (R13) ----
// FC epilogue vectorized: u read as float4 broadcasts -> 160 LDS/node vs 256.
__global__ void csr_agg1_final_kernel(const float* __restrict__ bias1,
                                      const int* __restrict__ node_group,
                                      const float* __restrict__ Wfc,
                                      const float* __restrict__ bfc,
                                      float* __restrict__ out) {
    __shared__ float Ws[128*32];
    __shared__ float Us[8][128];
    int t = threadIdx.x;
    for (int i = t; i < 128*32; i += 256) Ws[i] = Wfc[i];
    __syncthreads();

    int w = t >> 5, lane = t & 31;
    int d = blockIdx.x*8 + w;
    int start = g_row1[d], end = g_row1[d + 1];
    int hd = lane >> 3;
    float adv = __ldg(&g_adst1[d*4 + hd]);
    float4 acc = make_float4(0.f, 0.f, 0.f, 0.f);
    float wsum = 0.f;

    int j = start;
    for (; j + 4 <= end; j += 4) {
        int s0 = __ldg(&g_csr1[j]);
        int s1 = __ldg(&g_csr1[j + 1]);
        int s2 = __ldg(&g_csr1[j + 2]);
        int s3 = __ldg(&g_csr1[j + 3]);
        float a0 = __ldg(&g_asrc1[s0*4 + hd]);
        float a1 = __ldg(&g_asrc1[s1*4 + hd]);
        float a2 = __ldg(&g_asrc1[s2*4 + hd]);
        float a3 = __ldg(&g_asrc1[s3*4 + hd]);
        uint2 r0 = __ldg((const uint2*)(g_h1h + (size_t)s0*128 + lane*4));
        uint2 r1 = __ldg((const uint2*)(g_h1h + (size_t)s1*128 + lane*4));
        uint2 r2 = __ldg((const uint2*)(g_h1h + (size_t)s2*128 + lane*4));
        uint2 r3 = __ldg((const uint2*)(g_h1h + (size_t)s3*128 + lane*4));
        float e0 = a0 + adv; e0 = e0 > 0.f ? e0 : 0.2f*e0;
        float e1 = a1 + adv; e1 = e1 > 0.f ? e1 : 0.2f*e1;
        float e2 = a2 + adv; e2 = e2 > 0.f ? e2 : 0.2f*e2;
        float e3 = a3 + adv; e3 = e3 > 0.f ? e3 : 0.2f*e3;
        float w0 = __expf(e0), w1 = __expf(e1), w2 = __expf(e2), w3 = __expf(e3);
        float2 f0a = __half22float2(*(__half2*)&r0.x), f0b = __half22float2(*(__half2*)&r0.y);
        float2 f1a = __half22float2(*(__half2*)&r1.x), f1b = __half22float2(*(__half2*)&r1.y);
        float2 f2a = __half22float2(*(__half2*)&r2.x), f2b = __half22float2(*(__half2*)&r2.y);
        float2 f3a = __half22float2(*(__half2*)&r3.x), f3b = __half22float2(*(__half2*)&r3.y);
        acc.x += w0*f0a.x + w1*f1a.x + w2*f2a.x + w3*f3a.x;
        acc.y += w0*f0a.y + w1*f1a.y + w2*f2a.y + w3*f3a.y;
        acc.z += w0*f0b.x + w1*f1b.x + w2*f2b.x + w3*f3b.x;
        acc.w += w0*f0b.y + w1*f1b.y + w2*f2b.y + w3*f3b.y;
        wsum += (w0 + w1) + (w2 + w3);
    }
    for (; j < end; j++) {
        int s0 = __ldg(&g_csr1[j]);
        float a0 = __ldg(&g_asrc1[s0*4 + hd]);
        uint2 r0 = __ldg((const uint2*)(g_h1h + (size_t)s0*128 + lane*4));
        float e0 = a0 + adv; e0 = e0 > 0.f ? e0 : 0.2f*e0;
        float w0 = __expf(e0);
        float2 f0a = __half22float2(*(__half2*)&r0.x), f0b = __half22float2(*(__half2*)&r0.y);
        acc.x += w0*f0a.x; acc.y += w0*f0a.y; acc.z += w0*f0b.x; acc.w += w0*f0b.y;
        wsum += w0;
    }

    float inv = 1.f / (wsum + 1e-16f);
    float4 b1 = *(const float4*)(bias1 + lane*4);
    float4 xo = make_float4(acc.x*inv + b1.x, acc.y*inv + b1.y,
                            acc.z*inv + b1.z, acc.w*inv + b1.w);
    int g = __ldg(&node_group[d]);
    float4 gf = *(const float4*)(g_xgf + g*128 + lane*4);
    float4 af = *(const float4*)(g_adj + g*128 + lane*4);
    float pg = xo.x*gf.x + xo.y*gf.y + xo.z*gf.z + xo.w*gf.w;
    float pa = xo.x*af.x + xo.y*af.y + xo.z*af.z + xo.w*af.w;
    #pragma unroll
    for (int off = 16; off >= 1; off >>= 1) {
        pg += __shfl_xor_sync(0xffffffffu, pg, off);
        pa += __shfl_xor_sync(0xffffffffu, pa, off);
    }
    float4 u;
    u.x = xo.x + pg*gf.x + pa*af.x;
    u.y = xo.y + pg*gf.y + pa*af.y;
    u.z = xo.z + pg*gf.z + pa*af.z;
    u.w = xo.w + pg*gf.w + pa*af.w;
    *(float4*)&Us[w][lane*4] = u;
    __syncwarp();

    // FC: float4 broadcast u-reads (1 LDS.128 per 4 k) + 4 stride-32 Ws reads
    float accO = bfc[lane];
    const float4* ur4 = (const float4*)Us[w];
    #pragma unroll
    for (int k4 = 0; k4 < 32; k4++) {
        float4 uv = ur4[k4];
        int kb = k4*4;
        accO += uv.x*Ws[(kb+0)*32 + lane] + uv.y*Ws[(kb+1)*32 + lane]
              + uv.z*Ws[(kb+2)*32 + lane] + uv.w*Ws[(kb+3)*32 + lane];
    }
    out[d*32 + lane] = accO;
}

// ---------------- graph-2: fused softmax + agg + bias2, writes xgf & d_out tail ----
__global__ void csr_agg2_kernel(const float* __restrict__ bias2, float* __restrict__ dtail) {
    int gid = blockIdx.x * blockDim.x + threadIdx.x;
    int d = gid >> 5, lane = threadIdx.x & 31;
    if (d >= Gg) return;
    int start = g_row2[d], end = g_row2[d + 1];
    int hd = lane >> 3;
    float adv = __ldg(&g_adst2[d*4 + hd]);
    float4 acc = make_float4(0.f, 0.f, 0.f, 0.f);
    float wsum = 0.f;
    for (int j = start; j < end; j++) {
        int si = __ldg(&g_csr2[j]);
        float a = __ldg(&g_asrc2[si*4 + hd]);
        float4 hv = *(const float4*)(g_h2 + si*128 + lane*4);
        float e = a + adv;
        e = e > 0.f ? e : 0.2f*e;
        float w = __expf(e);
        acc.x += w*hv.x; acc.y += w*hv.y; acc.z += w*hv.z; acc.w += w*hv.w;
        wsum += w;
    }
    float inv = 1.f / (wsum + 1e-16f);
    float4 bv = *(const float4*)(bias2 + lane*4);
    float4 r = make_float4(acc.x*inv + bv.x, acc.y*inv + bv.y,
                           acc.z*inv + bv.z, acc.w*inv + bv.w);
    *(float4*)(g_xgf + d*128 + lane*4) = r;
    *(float4*)(dtail + d*128 + lane*4) = r;
}

// ---------------- adjacency mean over group edges ----------------
__global__ void adj_accum_kernel(const int* __restrict__ eg) {
    int gid = blockIdx.x * blockDim.x + threadIdx.x;
    int w = gid >> 5, lane = threadIdx.x & 31;
    if (w >= EGe) return;
    int a = eg[w];
    int b = eg[EGe + w];
    float4 v = *(const float4*)(g_xgf + b*128 + lane*4);
    redAddV4(g_adj + a*128 + lane*4, v.x, v.y, v.z, v.w);
    if (lane == 0) atomicAdd(&g_cnt[a], 1.f);
}

__global__ void adj_mean_kernel() {
    int i = blockIdx.x * blockDim.x + threadIdx.x;
    if (i < Gg*128) g_adj[i] = g_adj[i] / fmaxf(g_cnt[i >> 7], 1.f);
}

// ---------------- launch: THREE-way fork (graph-1 CSR | hgemm1 | group chain) -------
extern "C" void kernel_launch(void* const* d_in, const int* in_sizes, int n_in,
                              void* d_out, int out_size) {
    const float* x    = (const float*)d_in[0];
    const float* x_g  = (const float*)d_in[1];
    const int*   ei   = (const int*)d_in[2];
    const int*   eig  = (const int*)d_in[3];
    const int*   ngrp = (const int*)d_in[4];
    const float* W1   = (const float*)d_in[5];
    const float* as1  = (const float*)d_in[6];
    const float* ad1  = (const float*)d_in[7];
    const float* b1   = (const float*)d_in[8];
    const float* W2   = (const float*)d_in[9];
    const float* as2  = (const float*)d_in[10];
    const float* ad2  = (const float*)d_in[11];
    const float* b2   = (const float*)d_in[12];
    const float* Wfc  = (const float*)d_in[13];
    const float* bfc  = (const float*)d_in[14];
    float* out = (float*)d_out;

    const int HS_BYTES = 2 * 128 * HSTR * 2;   // 69632
    cudaFuncSetAttribute(hgemm1_kernel, cudaFuncAttributeMaxDynamicSharedMemorySize, HS_BYTES);

    cudaStream_t s2, s3;
    cudaStreamCreateWithFlags(&s2, cudaStreamNonBlocking);
    cudaStreamCreateWithFlags(&s3, cudaStreamNonBlocking);
    cudaEvent_t evFork, evA, evC;
    cudaEventCreateWithFlags(&evFork, cudaEventDisableTiming);
    cudaEventCreateWithFlags(&evA, cudaEventDisableTiming);
    cudaEventCreateWithFlags(&evC, cudaEventDisableTiming);

    cudaEventRecord(evFork, 0);
    cudaStreamWaitEvent(s2, evFork, 0);
    cudaStreamWaitEvent(s3, evFork, 0);

    // Branch B (stream 0): graph-1 CSR build (compressed: 4 launches)
    hist_kernel<<<(Ee + 255)/256, 256>>>(ei + Ee);
    scan1_kernel<<<NB1, SCAN_BS>>>();
    scan23_kernel<<<NB1, SCAN_BS>>>();

    // Branch A (s2): big GEMM
    hgemm1_kernel<<<(Nn + 127)/128, 256, HS_BYTES, s2>>>(x, W1, as1, ad1, Nn);
    cudaEventRecord(evA, s2);

    scatter_kernel<<<(Ee + Nn + 255)/256, 256>>>(ei, ei + Ee);

    // Branch C (s3): whole group-graph chain, independent of A and B
    build_csr2_kernel<<<1, 1024, 0, s3>>>(eig);
    gemm2_k128<<<(Gg + 63)/64, 256, 0, s3>>>(x_g, W2, as2, ad2, Gg);
    csr_agg2_kernel<<<(Gg*32 + 255)/256, 256, 0, s3>>>(b2, out + Nn*32);
    adj_accum_kernel<<<(EGe*32 + 255)/256, 256, 0, s3>>>(eig);
    adj_mean_kernel<<<(Gg*128 + 255)/256, 256, 0, s3>>>();
    cudaEventRecord(evC, s3);

    // join: final kernel needs all three branches
    cudaStreamWaitEvent(0, evA, 0);
    cudaStreamWaitEvent(0, evC, 0);
    csr_agg1_final_kernel<<<Nn/8, 256>>>(b1, ngrp, Wfc, bfc, out);

    cudaEventDestroy(evFork);
    cudaEventDestroy(evA);
    cudaEventDestroy(evC);
    cudaStreamDestroy(s2);
    cudaStreamDestroy(s3);
}